// round 4
// baseline (speedup 1.0000x reference)
#include <cuda_runtime.h>
#include <cstdint>

#define N_MAX 100000
#define D 64

__device__ __align__(16) int   g_deg [N_MAX];
__device__ __align__(16) float g_dinv[N_MAX];
__device__ __align__(16) float g_hs  [N_MAX * D];
__device__ __align__(16) float g_agg [N_MAX * D];
__device__ __align__(16) float g_x2  [N_MAX * D];

// ---------------- degree / norm ----------------

__global__ void k_init_deg(int n) {
    int i = blockIdx.x * blockDim.x + threadIdx.x;
    if (i < n) g_deg[i] = 1;                 // self-loop
}

__global__ void k_count(const int* __restrict__ ei, int E) {
    int e = blockIdx.x * blockDim.x + threadIdx.x;
    if (e < E) atomicAdd(&g_deg[ei[E + e]], 1);
}

__global__ void k_dinv(int n) {
    int i = blockIdx.x * blockDim.x + threadIdx.x;
    if (i < n) g_dinv[i] = rsqrtf((float)g_deg[i]);
}

// ---------------- fused GEMM: hs = (X @ W) * dinv; agg = hs ----------------

__global__ void __launch_bounds__(256, 2)
k_gemm(const float* __restrict__ X, const float* __restrict__ W, int n, int useX2) {
    __shared__ float Ws[D * D];
    __shared__ __align__(16) float xs[4][D];
    const float* Xp = useX2 ? g_x2 : X;
    int t = threadIdx.x;
    #pragma unroll
    for (int i = t; i < D * D; i += 256) Ws[i] = W[i];
    __syncthreads();

    int j = t & 63, g = t >> 6;
    float wcol[D];
    #pragma unroll
    for (int k = 0; k < D; k++) wcol[k] = Ws[k * D + j];

    int base = blockIdx.x * 32;
    for (int it = 0; it < 8; it++) {
        int node = base + it * 4 + g;
        __syncthreads();
        if (node < n) xs[g][j] = Xp[(size_t)node * D + j];
        __syncthreads();
        float acc = 0.f;
        const float4* xv4 = (const float4*)xs[g];
        #pragma unroll
        for (int k4 = 0; k4 < D / 4; k4++) {
            float4 xv = xv4[k4];
            acc = fmaf(xv.x, wcol[4 * k4 + 0], acc);
            acc = fmaf(xv.y, wcol[4 * k4 + 1], acc);
            acc = fmaf(xv.z, wcol[4 * k4 + 2], acc);
            acc = fmaf(xv.w, wcol[4 * k4 + 3], acc);
        }
        if (node < n) {
            float v = acc * g_dinv[node];
            size_t o = (size_t)node * D + j;
            g_hs[o]  = v;
            g_agg[o] = v;   // self-loop contribution
        }
    }
}

// ---------------- edge scatter: agg[dst] += hs[src] ----------------
// 16 threads per edge, one 16B vector reduction each.

__global__ void k_scatter(const int* __restrict__ ei, int E) {
    int tid = blockIdx.x * blockDim.x + threadIdx.x;
    int e = tid >> 4;
    if (e >= E) return;
    int lane = tid & 15;
    int src = ei[e];
    int dst = ei[E + e];
    float4 v = ((const float4*)(g_hs + (size_t)src * D))[lane];
    float* p = g_agg + (size_t)dst * D + lane * 4;
    unsigned long long gp;
    asm volatile("cvta.to.global.u64 %0, %1;" : "=l"(gp) : "l"(p));
    asm volatile("red.global.add.v4.f32 [%0], {%1,%2,%3,%4};"
                 :: "l"(gp), "f"(v.x), "f"(v.y), "f"(v.z), "f"(v.w)
                 : "memory");
}

// ---------------- epilogue: out = prelu(agg*dinv + b, a) ----------------
// dstX2 != 0 -> write to g_x2, else to out.

__global__ void k_epi(const float* __restrict__ b, const float* __restrict__ a,
                      float* __restrict__ out, int n, int dstX2) {
    int tid = blockIdx.x * blockDim.x + threadIdx.x;
    int node = tid >> 4;
    if (node >= n) return;
    int q = tid & 15;
    float* op = dstX2 ? g_x2 : out;
    float dinv = g_dinv[node];
    float4 v  = ((const float4*)g_agg)[(size_t)node * 16 + q];
    float4 bb = ((const float4*)b)[q];
    float4 aa = ((const float4*)a)[q];
    v.x = v.x * dinv + bb.x; v.x = (v.x >= 0.f) ? v.x : aa.x * v.x;
    v.y = v.y * dinv + bb.y; v.y = (v.y >= 0.f) ? v.y : aa.y * v.y;
    v.z = v.z * dinv + bb.z; v.z = (v.z >= 0.f) ? v.z : aa.z * v.z;
    v.w = v.w * dinv + bb.w; v.w = (v.w >= 0.f) ? v.w : aa.w * v.w;
    ((float4*)op)[(size_t)node * 16 + q] = v;
}

// ---------------- launch ----------------

extern "C" void kernel_launch(void* const* d_in, const int* in_sizes, int n_in,
                              void* d_out, int out_size) {
    const float* x  = (const float*)d_in[0];
    const int*   ei = (const int*)d_in[1];     // int32 (JAX x64 disabled)
    const float* W1 = (const float*)d_in[2];
    const float* b1 = (const float*)d_in[3];
    const float* a1 = (const float*)d_in[4];
    const float* W2 = (const float*)d_in[5];
    const float* b2 = (const float*)d_in[6];
    const float* a2 = (const float*)d_in[7];
    float* out = (float*)d_out;

    int n = in_sizes[0] / D;
    int E = in_sizes[1] / 2;

    int nb_n   = (n + 255) / 256;
    int nb_e   = (E + 255) / 256;
    int nb_gm  = (n + 31) / 32;
    int nb_sc  = (int)(((long long)E * 16 + 255) / 256);
    int nb_epi = (int)(((long long)n * 16 + 255) / 256);

    k_init_deg<<<nb_n, 256>>>(n);
    k_count   <<<nb_e, 256>>>(ei, E);
    k_dinv    <<<nb_n, 256>>>(n);

    // layer 1
    k_gemm   <<<nb_gm, 256>>>(x, W1, n, 0);
    k_scatter<<<nb_sc, 256>>>(ei, E);
    k_epi    <<<nb_epi, 256>>>(b1, a1, out, n, 1);   // -> g_x2

    // layer 2
    k_gemm   <<<nb_gm, 256>>>(x, W2, n, 1);          // reads g_x2
    k_scatter<<<nb_sc, 256>>>(ei, E);
    k_epi    <<<nb_epi, 256>>>(b2, a2, out, n, 0);   // -> d_out
}

// round 6
// speedup vs baseline: 1.3242x; 1.3242x over previous
#include <cuda_runtime.h>
#include <cstdint>

#define N_MAX 100000
#define D 64

__device__ __align__(16) int   g_deg [N_MAX];
__device__ __align__(16) float g_dinv[N_MAX];
__device__ __align__(16) float g_hs  [N_MAX * D];
__device__ __align__(16) float g_agg [N_MAX * D];

// ---------------- degree / norm ----------------

__global__ void k_init_deg(int n) {
    int i = blockIdx.x * blockDim.x + threadIdx.x;
    if (i < n) g_deg[i] = 1;                 // self-loop
}

__global__ void k_count(const int* __restrict__ ei, int E) {
    int e = blockIdx.x * blockDim.x + threadIdx.x;
    if (e < E) atomicAdd(&g_deg[ei[E + e]], 1);
}

__global__ void k_dinv(int n) {
    int i = blockIdx.x * blockDim.x + threadIdx.x;
    if (i < n) g_dinv[i] = rsqrtf((float)g_deg[i]);
}

// ---------------- fused GEMM ----------------
// mode 0: in = X (raw input)
// mode 1: in = prelu(g_agg * dinv + b, a)   (fused layer-1 epilogue)
// output: hs = (in @ W) * dinv ; agg = hs (self-loop init)
//
// 256 threads, 64-node tile. Thread owns output column j = t&63 with the W
// column register-cached; group g = t>>6 sweeps 16 nodes in batches of 4
// (4 independent accumulator chains for ILP). X tile staged via smem,
// broadcast LDS.128 reads.

__global__ void __launch_bounds__(256, 2)
k_gemm(const float* __restrict__ X, const float* __restrict__ W,
       const float* __restrict__ bp, const float* __restrict__ ap,
       int n, int mode)
{
    __shared__ __align__(16) float  Ws[D * D];
    __shared__ __align__(16) float4 xs[64][16];
    int t = threadIdx.x;

    #pragma unroll
    for (int i = 0; i < 4; i++)
        ((float4*)Ws)[t + 256 * i] = ((const float4*)W)[t + 256 * i];

    int base = blockIdx.x * 64;

    // stage input tile (coalesced float4), applying fused epilogue in mode 1
    #pragma unroll
    for (int r = 0; r < 4; r++) {
        int i = t + 256 * r;
        int node = base + (i >> 4);
        int k4 = i & 15;
        float4 v = make_float4(0.f, 0.f, 0.f, 0.f);
        if (node < n) {
            if (mode == 0) {
                v = ((const float4*)X)[(size_t)node * 16 + k4];
            } else {
                v = ((const float4*)g_agg)[(size_t)node * 16 + k4];
                float dv = g_dinv[node];
                float4 bb = ((const float4*)bp)[k4];
                float4 aa = ((const float4*)ap)[k4];
                v.x = v.x * dv + bb.x; v.x = (v.x >= 0.f) ? v.x : aa.x * v.x;
                v.y = v.y * dv + bb.y; v.y = (v.y >= 0.f) ? v.y : aa.y * v.y;
                v.z = v.z * dv + bb.z; v.z = (v.z >= 0.f) ? v.z : aa.z * v.z;
                v.w = v.w * dv + bb.w; v.w = (v.w >= 0.f) ? v.w : aa.w * v.w;
            }
        }
        xs[i >> 4][k4] = v;
    }
    __syncthreads();

    int j = t & 63, g = t >> 6;
    float wcol[D];
    #pragma unroll
    for (int k = 0; k < D; k++) wcol[k] = Ws[k * D + j];

    #pragma unroll
    for (int batch = 0; batch < 4; batch++) {
        int n0 = g * 16 + batch * 4;               // local node index
        float acc0 = 0.f, acc1 = 0.f, acc2 = 0.f, acc3 = 0.f;
        #pragma unroll
        for (int k4 = 0; k4 < 16; k4++) {
            float4 x0 = xs[n0 + 0][k4];
            float4 x1 = xs[n0 + 1][k4];
            float4 x2 = xs[n0 + 2][k4];
            float4 x3 = xs[n0 + 3][k4];
            float w0 = wcol[4 * k4 + 0], w1 = wcol[4 * k4 + 1];
            float w2 = wcol[4 * k4 + 2], w3 = wcol[4 * k4 + 3];
            acc0 = fmaf(x0.x, w0, acc0); acc0 = fmaf(x0.y, w1, acc0);
            acc0 = fmaf(x0.z, w2, acc0); acc0 = fmaf(x0.w, w3, acc0);
            acc1 = fmaf(x1.x, w0, acc1); acc1 = fmaf(x1.y, w1, acc1);
            acc1 = fmaf(x1.z, w2, acc1); acc1 = fmaf(x1.w, w3, acc1);
            acc2 = fmaf(x2.x, w0, acc2); acc2 = fmaf(x2.y, w1, acc2);
            acc2 = fmaf(x2.z, w2, acc2); acc2 = fmaf(x2.w, w3, acc2);
            acc3 = fmaf(x3.x, w0, acc3); acc3 = fmaf(x3.y, w1, acc3);
            acc3 = fmaf(x3.z, w2, acc3); acc3 = fmaf(x3.w, w3, acc3);
        }
        float accs[4] = {acc0, acc1, acc2, acc3};
        #pragma unroll
        for (int q = 0; q < 4; q++) {
            int node = base + n0 + q;
            if (node < n) {
                float v = accs[q] * g_dinv[node];
                size_t o = (size_t)node * D + j;
                g_hs[o]  = v;
                g_agg[o] = v;                      // self-loop contribution
            }
        }
    }
}

// ---------------- edge scatter: agg[dst] += hs[src] ----------------

__global__ void k_scatter(const int* __restrict__ ei, int E) {
    int tid = blockIdx.x * blockDim.x + threadIdx.x;
    int e = tid >> 4;
    if (e >= E) return;
    int lane = tid & 15;
    int src = ei[e];
    int dst = ei[E + e];
    float4 v = ((const float4*)(g_hs + (size_t)src * D))[lane];
    float* p = g_agg + (size_t)dst * D + lane * 4;
    unsigned long long gp;
    asm volatile("cvta.to.global.u64 %0, %1;" : "=l"(gp) : "l"(p));
    asm volatile("red.global.add.v4.f32 [%0], {%1,%2,%3,%4};"
                 :: "l"(gp), "f"(v.x), "f"(v.y), "f"(v.z), "f"(v.w)
                 : "memory");
}

// ---------------- final epilogue: out = prelu(agg*dinv + b, a) ----------------

__global__ void k_epi(const float* __restrict__ b, const float* __restrict__ a,
                      float* __restrict__ out, int n) {
    int tid = blockIdx.x * blockDim.x + threadIdx.x;
    int node = tid >> 4;
    if (node >= n) return;
    int q = tid & 15;
    float dinv = g_dinv[node];
    float4 v  = ((const float4*)g_agg)[(size_t)node * 16 + q];
    float4 bb = ((const float4*)b)[q];
    float4 aa = ((const float4*)a)[q];
    v.x = v.x * dinv + bb.x; v.x = (v.x >= 0.f) ? v.x : aa.x * v.x;
    v.y = v.y * dinv + bb.y; v.y = (v.y >= 0.f) ? v.y : aa.y * v.y;
    v.z = v.z * dinv + bb.z; v.z = (v.z >= 0.f) ? v.z : aa.z * v.z;
    v.w = v.w * dinv + bb.w; v.w = (v.w >= 0.f) ? v.w : aa.w * v.w;
    ((float4*)out)[(size_t)node * 16 + q] = v;
}

// ---------------- launch ----------------

extern "C" void kernel_launch(void* const* d_in, const int* in_sizes, int n_in,
                              void* d_out, int out_size) {
    const float* x  = (const float*)d_in[0];
    const int*   ei = (const int*)d_in[1];     // int32 (JAX x64 disabled)
    const float* W1 = (const float*)d_in[2];
    const float* b1 = (const float*)d_in[3];
    const float* a1 = (const float*)d_in[4];
    const float* W2 = (const float*)d_in[5];
    const float* b2 = (const float*)d_in[6];
    const float* a2 = (const float*)d_in[7];
    float* out = (float*)d_out;

    int n = in_sizes[0] / D;
    int E = in_sizes[1] / 2;

    int nb_n   = (n + 255) / 256;
    int nb_e   = (E + 255) / 256;
    int nb_gm  = (n + 63) / 64;
    int nb_sc  = (int)(((long long)E * 16 + 255) / 256);
    int nb_epi = (int)(((long long)n * 16 + 255) / 256);

    k_init_deg<<<nb_n, 256>>>(n);
    k_count   <<<nb_e, 256>>>(ei, E);
    k_dinv    <<<nb_n, 256>>>(n);

    // layer 1
    k_gemm   <<<nb_gm, 256>>>(x, W1, b1, a1, n, 0);
    k_scatter<<<nb_sc, 256>>>(ei, E);

    // layer 2 (epilogue-1 fused into GEMM staging)
    k_gemm   <<<nb_gm, 256>>>(x, W2, b1, a1, n, 1);
    k_scatter<<<nb_sc, 256>>>(ei, E);
    k_epi    <<<nb_epi, 256>>>(b2, a2, out, n);
}